// round 14
// baseline (speedup 1.0000x reference)
#include <cuda_runtime.h>
#include <cuda_bf16.h>

#define NPTS  16384
#define NNBR  32
#define CIN   16
#define COUT  16
#define NB    16
#define GAMMA 10.0f
#define EPSF  1e-12f

// Scratch (allocation-free rule: __device__ globals)
__device__ float4     g_inputT[NPTS * 4];   // [n*4+q] : channels 4q..4q+3 of point n
__device__ float4     g_coords4[NPTS];      // padded coords
__device__ ulonglong2 g_Wt2v[1024];         // W repacked: entry (o*16+b)*4+c2 =
                                            // ((W[o][4c2][b],W[o][4c2+1][b]),(W[o][4c2+2][b],W[o][4c2+3][b]))

// ---------------- f32x2 helpers (sm_103a packed fp32) ----------------------
__device__ __forceinline__ unsigned long long ffma2(unsigned long long a,
                                                    unsigned long long b,
                                                    unsigned long long c) {
    unsigned long long d;
    asm("fma.rn.f32x2 %0, %1, %2, %3;" : "=l"(d) : "l"(a), "l"(b), "l"(c));
    return d;
}
__device__ __forceinline__ unsigned long long dup2(float x) {
    unsigned long long d;
    asm("mov.b64 %0, {%1, %1};" : "=l"(d) : "f"(x));
    return d;
}
__device__ __forceinline__ unsigned long long pack2(float lo, float hi) {
    unsigned long long d;
    asm("mov.b64 %0, {%1, %2};" : "=l"(d) : "f"(lo), "f"(hi));
    return d;
}
__device__ __forceinline__ float2 unpack2(unsigned long long v) {
    float2 f;
    asm("mov.b64 {%0, %1}, %2;" : "=f"(f.x), "=f"(f.y) : "l"(v));
    return f;
}
__device__ __forceinline__ float ex2(float x) {
    float y;
    asm("ex2.approx.ftz.f32 %0, %1;" : "=f"(y) : "f"(x));
    return y;
}

// ---------------------------------------------------------------------------
// Prep: transpose input (C,N)->(N,C) float4 rows (2 points/thread, float2
// loads), pad coords, repack W into channel-pair u64s.
// ---------------------------------------------------------------------------
__global__ void prep_kernel(const float* __restrict__ input,
                            const float* __restrict__ coords,
                            const float* __restrict__ W) {
    const int idx = blockIdx.x * blockDim.x + threadIdx.x;   // 0 .. 32767
    const int q  = idx >> 13;           // 0..3 channel quartet
    const int n0 = (idx & 8191) * 2;    // even point index

    const float2* in2 = (const float2*)input;
    const float2 v0 = in2[((4 * q + 0) * NPTS + n0) >> 1];
    const float2 v1 = in2[((4 * q + 1) * NPTS + n0) >> 1];
    const float2 v2 = in2[((4 * q + 2) * NPTS + n0) >> 1];
    const float2 v3 = in2[((4 * q + 3) * NPTS + n0) >> 1];
    g_inputT[(n0 + 0) * 4 + q] = make_float4(v0.x, v1.x, v2.x, v3.x);
    g_inputT[(n0 + 1) * 4 + q] = make_float4(v0.y, v1.y, v2.y, v3.y);

    if (q == 0) {
        const float2* co2 = (const float2*)(coords + 3 * n0);   // 6 floats, 8B-aligned
        const float2 a = co2[0], b = co2[1], c = co2[2];
        g_coords4[n0 + 0] = make_float4(a.x, a.y, b.x, 0.0f);
        g_coords4[n0 + 1] = make_float4(b.y, c.x, c.y, 0.0f);
    }
    if (idx < 1024) {
        const int row = idx >> 2;        // o*16 + b
        const int c2  = idx & 3;
        const int o = row >> 4, b = row & 15;
        ulonglong2 w2;
        w2.x = pack2(W[(o * 16 + 4 * c2 + 0) * 16 + b], W[(o * 16 + 4 * c2 + 1) * 16 + b]);
        w2.y = pack2(W[(o * 16 + 4 * c2 + 2) * 16 + b], W[(o * 16 + 4 * c2 + 3) * 16 + b]);
        g_Wt2v[idx] = w2;
    }
}

// ---------------------------------------------------------------------------
// Main: 4 lanes/point, lane t owns bases 4t..4t+3 (R12 accumulator layout,
// verified). Shuffle storm replaced by smem staging:
//  per neighbor QUAD: lane t gathers the full 16-ch vector of nbr 4kk+t
//  (4 LDG.128), stages to smem (4 STS.128); after syncwarp all lanes read
//  x-pairs via LDS.128 broadcast (point stride 84 words -> conflict-free).
//  r/e0 computed once per neighbor by its owner lane, shared by 2 SHFL/nbr.
//  u: 4 ex2/nbr/lane (zero redundancy). 32 FFMA2/nbr/lane.
// Epilogue: FFMA2 vs channel-pair W in smem, width-4 butterfly (R12 code).
// ---------------------------------------------------------------------------
__global__ __launch_bounds__(256, 2)
void conv_kernel(const float* __restrict__ centers,
                 const float* __restrict__ mask,
                 const int*   __restrict__ neighbors,
                 float*       __restrict__ out) {
    __shared__ ulonglong2 smWt[COUT * CIN * 5];   // 20480 B, row pad 5
    __shared__ float      smX[8][672];            // 8 warps x (8 pts x 84 words)

    const int tid = threadIdx.x;
    #pragma unroll
    for (int e = 0; e < 4; e++) {
        const int gi = tid + 256 * e;
        smWt[(gi >> 2) * 5 + (gi & 3)] = g_Wt2v[gi];
    }
    __syncthreads();

    const int t    = tid & 3;          // basis-quartet owner / quad-slot writer
    const int pl   = tid >> 2;         // point within block (0..63)
    const int n    = blockIdx.x * 64 + pl;
    const int warp = tid >> 5;
    const int pw   = pl & 7;           // point within warp (0..7)
    float* myX   = &smX[warp][0];
    float* slotW = myX + 84 * pw + 20 * t;   // this lane's staging slot

    const float NGL2 = -GAMMA * 1.4426950408889634f;
    float cs[4], K[4];
    #pragma unroll
    for (int bb = 0; bb < 4; bb++) {
        const float cb = __ldg(&centers[4 * t + bb]);
        cs[bb] = -2.0f * NGL2 * cb;
        K[bb]  = NGL2 * cb * cb;
    }
    const float4 pc = g_coords4[n];

    unsigned long long acc2[4][8];
    #pragma unroll
    for (int bb = 0; bb < 4; bb++)
        #pragma unroll
        for (int cp = 0; cp < 8; cp++) acc2[bb][cp] = 0ull;

    const int*   nbp = neighbors + n * NNBR;
    const float* mkp = mask + n * NNBR;
    const uint4* Xg  = (const uint4*)g_inputT;

    // Prefetch quad 0 (own neighbor = 4*0 + t)
    int    nbr_own = __ldg(&nbp[t]);
    float  m_own   = __ldg(&mkp[t]);
    float4 cc      = __ldg(&g_coords4[nbr_own]);
    uint4 X0 = __ldg(&Xg[nbr_own * 4 + 0]);
    uint4 X1 = __ldg(&Xg[nbr_own * 4 + 1]);
    uint4 X2 = __ldg(&Xg[nbr_own * 4 + 2]);
    uint4 X3 = __ldg(&Xg[nbr_own * 4 + 3]);

    for (int kk = 0; kk < 8; kk++) {
        // r, e0 for own neighbor (from current cc/m_own)
        const float dx = cc.x - pc.x;
        const float dy = cc.y - pc.y;
        const float dz = cc.z - pc.z;
        const float r2 = fmaf(dx, dx, fmaf(dy, dy, fmaf(dz, dz, EPSF)));
        const float r_own  = sqrtf(r2);
        const float e0_own = fmaf(NGL2, r2, __log2f(m_own));

        // Stage own neighbor's full X
        *(uint4*)(slotW + 0)  = X0;
        *(uint4*)(slotW + 4)  = X1;
        *(uint4*)(slotW + 8)  = X2;
        *(uint4*)(slotW + 12) = X3;

        // Early prefetch of next quad's scalars
        if (kk < 7) {
            nbr_own = __ldg(&nbp[4 * (kk + 1) + t]);
            m_own   = __ldg(&mkp[4 * (kk + 1) + t]);
        }
        __syncwarp();
        if (kk < 7) {
            cc = __ldg(&g_coords4[nbr_own]);
            X0 = __ldg(&Xg[nbr_own * 4 + 0]);
            X1 = __ldg(&Xg[nbr_own * 4 + 1]);
            X2 = __ldg(&Xg[nbr_own * 4 + 2]);
            X3 = __ldg(&Xg[nbr_own * 4 + 3]);
        }

        #pragma unroll
        for (int j = 0; j < 4; j++) {
            const float r  = __shfl_sync(0xFFFFFFFFu, r_own,  j, 4);
            const float e0 = __shfl_sync(0xFFFFFFFFu, e0_own, j, 4);
            unsigned long long ud[4];
            #pragma unroll
            for (int bb = 0; bb < 4; bb++)
                ud[bb] = dup2(ex2(fmaf(r, cs[bb], e0 + K[bb])));

            const ulonglong2* xs = (const ulonglong2*)(myX + 84 * pw + 20 * j);
            #pragma unroll
            for (int qq = 0; qq < 4; qq++) {
                const ulonglong2 xp = xs[qq];   // (x4qq,x4qq+1),(x4qq+2,x4qq+3)
                #pragma unroll
                for (int bb = 0; bb < 4; bb++) {
                    acc2[bb][2 * qq + 0] = ffma2(ud[bb], xp.x, acc2[bb][2 * qq + 0]);
                    acc2[bb][2 * qq + 1] = ffma2(ud[bb], xp.y, acc2[bb][2 * qq + 1]);
                }
            }
        }
        __syncwarp();   // WAR: all reads done before next quad's STS
    }

    // Epilogue (verified in R12): s(o) = sum_{bb,cp} W2[o][4t+bb][cp] . acc2[bb][cp]
    float po[4];
    #pragma unroll
    for (int o = 0; o < COUT; o++) {
        unsigned long long s2 = 0ull;
        #pragma unroll
        for (int bb = 0; bb < 4; bb++) {
            const ulonglong2* wr = &smWt[(o * CIN + 4 * t + bb) * 5];
            #pragma unroll
            for (int c2 = 0; c2 < 4; c2++) {
                const ulonglong2 w2 = wr[c2];
                s2 = ffma2(w2.x, acc2[bb][2 * c2 + 0], s2);
                s2 = ffma2(w2.y, acc2[bb][2 * c2 + 1], s2);
            }
        }
        const float2 sf = unpack2(s2);
        float s = sf.x + sf.y;
        s += __shfl_xor_sync(0xFFFFFFFFu, s, 1, 4);
        s += __shfl_xor_sync(0xFFFFFFFFu, s, 2, 4);
        if ((o >> 2) == t) po[o & 3] = s;
    }

    #pragma unroll
    for (int j = 0; j < 4; j++)
        out[(4 * t + j) * NPTS + n] = po[j];
}

// ---------------------------------------------------------------------------
extern "C" void kernel_launch(void* const* d_in, const int* in_sizes, int n_in,
                              void* d_out, int out_size) {
    const float* input     = (const float*)d_in[0];   // (16, 16384)
    const float* coords    = (const float*)d_in[1];   // (16384, 3)
    const float* W         = (const float*)d_in[2];   // (16, 16, 16)
    const float* centers   = (const float*)d_in[3];   // (16,)
    const float* mask      = (const float*)d_in[4];   // (16384, 32)
    const int*   neighbors = (const int*)d_in[5];     // (16384, 32)
    float*       out       = (float*)d_out;           // (16, 16384)

    prep_kernel<<<128, 256>>>(input, coords, W);
    conv_kernel<<<NPTS / 64, 256>>>(centers, mask, neighbors, out);
}

// round 15
// speedup vs baseline: 1.4189x; 1.4189x over previous
#include <cuda_runtime.h>
#include <cuda_bf16.h>

#define NPTS  16384
#define NNBR  32
#define CIN   16
#define COUT  16
#define NB    16
#define GAMMA 10.0f
#define EPSF  1e-12f

// Scratch (allocation-free rule: __device__ globals)
__device__ float4     g_inputT[NPTS * 4];   // [n*4+q] : channels 4q..4q+3 of point n
__device__ float4     g_coords4[NPTS];      // padded coords
__device__ ulonglong2 g_Wt3[1024];          // W tiled for 2x2-role epilogue:
// entry [(o*8 + j)*8 + tb*4 + c2] = ((W[o][4c2][8tb+j],W[o][4c2+1][8tb+j]),
//                                    (W[o][4c2+2][8tb+j],W[o][4c2+3][8tb+j]))

// ---------------- f32x2 / fast-math helpers (sm_103a) ----------------------
__device__ __forceinline__ unsigned long long ffma2(unsigned long long a,
                                                    unsigned long long b,
                                                    unsigned long long c) {
    unsigned long long d;
    asm("fma.rn.f32x2 %0, %1, %2, %3;" : "=l"(d) : "l"(a), "l"(b), "l"(c));
    return d;
}
__device__ __forceinline__ unsigned long long dup2(float x) {
    unsigned long long d;
    asm("mov.b64 %0, {%1, %1};" : "=l"(d) : "f"(x));
    return d;
}
__device__ __forceinline__ unsigned long long pack2(float lo, float hi) {
    unsigned long long d;
    asm("mov.b64 %0, {%1, %2};" : "=l"(d) : "f"(lo), "f"(hi));
    return d;
}
__device__ __forceinline__ float2 unpack2(unsigned long long v) {
    float2 f;
    asm("mov.b64 {%0, %1}, %2;" : "=f"(f.x), "=f"(f.y) : "l"(v));
    return f;
}
__device__ __forceinline__ float ex2(float x) {
    float y;
    asm("ex2.approx.ftz.f32 %0, %1;" : "=f"(y) : "f"(x));
    return y;
}
__device__ __forceinline__ float lg2(float x) {
    float y;
    asm("lg2.approx.ftz.f32 %0, %1;" : "=f"(y) : "f"(x));
    return y;
}

// ---------------------------------------------------------------------------
// Prep: transpose input (C,N)->(N,C) float4 rows (2 pts/thread), pad coords,
// build the role-tiled W table.
// ---------------------------------------------------------------------------
__global__ void prep_kernel(const float* __restrict__ input,
                            const float* __restrict__ coords,
                            const float* __restrict__ W) {
    const int idx = blockIdx.x * blockDim.x + threadIdx.x;   // 0 .. 32767
    const int q  = idx >> 13;           // 0..3 channel quartet
    const int n0 = (idx & 8191) * 2;    // even point index

    const float2* in2 = (const float2*)input;
    const float2 v0 = in2[((4 * q + 0) * NPTS + n0) >> 1];
    const float2 v1 = in2[((4 * q + 1) * NPTS + n0) >> 1];
    const float2 v2 = in2[((4 * q + 2) * NPTS + n0) >> 1];
    const float2 v3 = in2[((4 * q + 3) * NPTS + n0) >> 1];
    g_inputT[(n0 + 0) * 4 + q] = make_float4(v0.x, v1.x, v2.x, v3.x);
    g_inputT[(n0 + 1) * 4 + q] = make_float4(v0.y, v1.y, v2.y, v3.y);

    if (q == 0) {
        const float2* co2 = (const float2*)(coords + 3 * n0);   // 6 floats
        const float2 a = co2[0], b = co2[1], c = co2[2];
        g_coords4[n0 + 0] = make_float4(a.x, a.y, b.x, 0.0f);
        g_coords4[n0 + 1] = make_float4(b.y, c.x, c.y, 0.0f);
    }
    if (idx < 1024) {
        const int entry = idx & 7;       // tb*4 + c2
        const int tb = entry >> 2, c2 = entry & 3;
        const int row = idx >> 3;        // o*8 + j
        const int o = row >> 3, j = row & 7;
        const int b = 8 * tb + j;
        ulonglong2 w2;
        w2.x = pack2(W[(o * 16 + 4 * c2 + 0) * 16 + b], W[(o * 16 + 4 * c2 + 1) * 16 + b]);
        w2.y = pack2(W[(o * 16 + 4 * c2 + 2) * 16 + b], W[(o * 16 + 4 * c2 + 3) * 16 + b]);
        g_Wt3[idx] = w2;
    }
}

// ---------------------------------------------------------------------------
// Main: 4 lanes/point, OUTPUT-TILED 2x2: lane role (tb,tc) owns
// A[8tb..8tb+7][8tc..8tc+7] (acc = 32 f32x2 over channel pairs).
// Per neighbor, per lane: load own 8 channels (2 LDG.128, no redistribution),
// compute own 8 u's (2x exp redundancy), 32 FFMA2. No mainloop SHFL/LDS/STS.
// Epilogue: 512 FFMA2 vs role-tiled W in smem (conflict-free by role banks),
// width-4 butterfly, lane t writes outputs 4t..4t+3.
// ---------------------------------------------------------------------------
__global__ __launch_bounds__(256, 2)
void conv_kernel(const float* __restrict__ centers,
                 const float* __restrict__ mask,
                 const int*   __restrict__ neighbors,
                 float*       __restrict__ out) {
    __shared__ ulonglong2 smW3[1024];   // 16KB

    const int tid = threadIdx.x;
    #pragma unroll
    for (int e = 0; e < 4; e++)
        smW3[tid + 256 * e] = g_Wt3[tid + 256 * e];
    __syncthreads();

    const int t  = tid & 3;
    const int tb = t >> 1;           // basis-octet owner
    const int tc = t & 1;            // channel-octet owner
    const int pl = tid >> 2;         // point within block (0..63)
    const int n  = blockIdx.x * 64 + pl;

    const float NGL2 = -GAMMA * 1.4426950408889634f;
    float cs[8], K[8];
    #pragma unroll
    for (int bb = 0; bb < 8; bb++) {
        const float cb = __ldg(&centers[8 * tb + bb]);
        cs[bb] = -2.0f * NGL2 * cb;
        K[bb]  = NGL2 * cb * cb;
    }
    const float4 pc = g_coords4[n];

    unsigned long long acc2[8][4];   // [local basis][channel pair]
    #pragma unroll
    for (int bb = 0; bb < 8; bb++)
        #pragma unroll
        for (int cp = 0; cp < 4; cp++) acc2[bb][cp] = 0ull;

    const int*   nbp = neighbors + n * NNBR;
    const float* mkp = mask + n * NNBR;
    const ulonglong2* inT2 = (const ulonglong2*)g_inputT;

    #pragma unroll 4
    for (int k = 0; k < NNBR; k++) {
        const int   nbr = __ldg(&nbp[k]);
        const float m   = __ldg(&mkp[k]);
        const float4 cc = g_coords4[nbr];
        const float dx = cc.x - pc.x;
        const float dy = cc.y - pc.y;
        const float dz = cc.z - pc.z;
        const float r2 = fmaf(dx, dx, fmaf(dy, dy, fmaf(dz, dz, EPSF)));
        const float r  = sqrtf(r2);
        const float e0 = fmaf(NGL2, r2, lg2(m));

        const ulonglong2 X0 = __ldg(&inT2[nbr * 4 + 2 * tc + 0]); // ch 8tc..8tc+3
        const ulonglong2 X1 = __ldg(&inT2[nbr * 4 + 2 * tc + 1]); // ch 8tc+4..8tc+7

        #pragma unroll
        for (int bb = 0; bb < 8; bb++) {
            const unsigned long long ud =
                dup2(ex2(fmaf(r, cs[bb], e0 + K[bb])));
            acc2[bb][0] = ffma2(ud, X0.x, acc2[bb][0]);
            acc2[bb][1] = ffma2(ud, X0.y, acc2[bb][1]);
            acc2[bb][2] = ffma2(ud, X1.x, acc2[bb][2]);
            acc2[bb][3] = ffma2(ud, X1.y, acc2[bb][3]);
        }
    }

    // Epilogue: s(o) = sum_{bb,cp} W3[o][bb][role] . acc2[bb][cp]
    float po[4];
    #pragma unroll
    for (int o = 0; o < COUT; o++) {
        unsigned long long s2 = 0ull;
        #pragma unroll
        for (int bb = 0; bb < 8; bb++) {
            const ulonglong2* rowp = &smW3[(o * 8 + bb) * 8 + tb * 4 + 2 * tc];
            const ulonglong2 wa = rowp[0];   // channel pairs 0,1
            const ulonglong2 wb = rowp[1];   // channel pairs 2,3
            s2 = ffma2(wa.x, acc2[bb][0], s2);
            s2 = ffma2(wa.y, acc2[bb][1], s2);
            s2 = ffma2(wb.x, acc2[bb][2], s2);
            s2 = ffma2(wb.y, acc2[bb][3], s2);
        }
        const float2 sf = unpack2(s2);
        float s = sf.x + sf.y;
        s += __shfl_xor_sync(0xFFFFFFFFu, s, 1, 4);
        s += __shfl_xor_sync(0xFFFFFFFFu, s, 2, 4);
        if ((o >> 2) == t) po[o & 3] = s;
    }

    #pragma unroll
    for (int j = 0; j < 4; j++)
        out[(4 * t + j) * NPTS + n] = po[j];
}

// ---------------------------------------------------------------------------
extern "C" void kernel_launch(void* const* d_in, const int* in_sizes, int n_in,
                              void* d_out, int out_size) {
    const float* input     = (const float*)d_in[0];   // (16, 16384)
    const float* coords    = (const float*)d_in[1];   // (16384, 3)
    const float* W         = (const float*)d_in[2];   // (16, 16, 16)
    const float* centers   = (const float*)d_in[3];   // (16,)
    const float* mask      = (const float*)d_in[4];   // (16384, 32)
    const int*   neighbors = (const int*)d_in[5];     // (16384, 32)
    float*       out       = (float*)d_out;           // (16, 16384)

    prep_kernel<<<128, 256>>>(input, coords, W);
    conv_kernel<<<NPTS / 64, 256>>>(centers, mask, neighbors, out);
}